// round 3
// baseline (speedup 1.0000x reference)
#include <cuda_runtime.h>
#include <math.h>

#define BTd 4
#define Ld 512
#define F1Dd 46
#define F2Dd 44
#define Cd 32
#define Kd 64
#define NBLKd 4
#define PWSTRIDE 109   // F2D + 2C + 1

// Scratch (device globals: no allocation allowed)
__device__ float g_x[BTd * Cd * Ld];
__device__ float g_y[BTd * Cd * Ld];
__device__ float g_eL[BTd * Ld * Kd];
__device__ float g_eR[BTd * Ld * Kd];
__device__ float g_pe[Ld * 32];   // pe_half: [l][0:16]=sin, [16:32]=cos
__device__ float g_sep[Ld];       // log(d+1)
__device__ unsigned g_cnt[16];    // grid-barrier slots (self-resetting)

// ---------------------------------------------------------------------------
// f32x2 packed-FMA helpers (sm_100+)
// ---------------------------------------------------------------------------
static __device__ __forceinline__ unsigned long long pack2(float x, float y) {
    unsigned long long r;
    asm("mov.b64 %0, {%1,%2};" : "=l"(r) : "f"(x), "f"(y));
    return r;
}
static __device__ __forceinline__ void unpack2(unsigned long long v, float& x, float& y) {
    asm("mov.b64 {%0,%1}, %2;" : "=f"(x), "=f"(y) : "l"(v));
}
static __device__ __forceinline__ unsigned long long ffma2(unsigned long long a,
                                                           unsigned long long b,
                                                           unsigned long long c) {
    unsigned long long d;
    asm("fma.rn.f32x2 %0, %1, %2, %3;" : "=l"(d) : "l"(a), "l"(b), "l"(c));
    return d;
}

// ---------------------------------------------------------------------------
// software grid barrier: 128 co-resident CTAs, slot b.
// Each CTA adds twice (arrive, then observe). 256th add resets slot -> ready
// for the next launch/replay. Deterministic; no ABA.
// ---------------------------------------------------------------------------
#define NB_TOWER 128u
static __device__ __forceinline__ void grid_bar(int b) {
    __syncthreads();
    if (threadIdx.x == 0) {
        __threadfence();
        unsigned t = atomicAdd(&g_cnt[b], 1u);
        if (t < NB_TOWER - 1u) {
            while (*((volatile unsigned*)&g_cnt[b]) < NB_TOWER) {}
        }
        __threadfence();
        unsigned u = atomicAdd(&g_cnt[b], 1u);
        if (u == 2u * NB_TOWER - 1u) {
            *((volatile unsigned*)&g_cnt[b]) = 0u;
        }
    }
    __syncthreads();
}

// ---------------------------------------------------------------------------
// block reduce (512 threads): sum of (a, b) broadcast to all threads
// ---------------------------------------------------------------------------
static __device__ __forceinline__ float2 blockReduce2(float a, float b) {
    __shared__ float sa[16], sb[16], res[2];
    #pragma unroll
    for (int off = 16; off > 0; off >>= 1) {
        a += __shfl_down_sync(0xffffffffu, a, off);
        b += __shfl_down_sync(0xffffffffu, b, off);
    }
    int wid = threadIdx.x >> 5, lid = threadIdx.x & 31;
    if (lid == 0) { sa[wid] = a; sb[wid] = b; }
    __syncthreads();
    if (threadIdx.x == 0) {
        float ta = 0.f, tb = 0.f;
        #pragma unroll
        for (int i = 0; i < 16; ++i) { ta += sa[i]; tb += sb[i]; }
        res[0] = ta; res[1] = tb;
    }
    __syncthreads();
    return make_float2(res[0], res[1]);
}

static __device__ __forceinline__ float conv_row(const float* __restrict__ xb,
                                                 const float* __restrict__ sw, int l) {
    float a0 = 0.f, a1 = 0.f, a2 = 0.f, a3 = 0.f;
    #pragma unroll
    for (int ci = 0; ci < Cd; ci += 4) {
        #pragma unroll
        for (int q = 0; q < 4; ++q) {
            const float* xr = xb + (ci + q) * Ld;
            float xm = (l > 0)      ? xr[l - 1] : 0.f;
            float x0 = xr[l];
            float xp = (l < Ld - 1) ? xr[l + 1] : 0.f;
            float s = sw[(ci + q) * 3 + 0] * xm + sw[(ci + q) * 3 + 1] * x0
                    + sw[(ci + q) * 3 + 2] * xp;
            if (q == 0) a0 += s; else if (q == 1) a1 += s;
            else if (q == 2) a2 += s; else a3 += s;
        }
    }
    return (a0 + a1) + (a2 + a3);
}

// ---------------------------------------------------------------------------
// Persistent tower kernel: tables + proj1d + 4 residual blocks + eL/eR.
// grid = 128 blocks x 512 threads (single wave; software grid barriers).
// ---------------------------------------------------------------------------
__global__ __launch_bounds__(512) void k_tower(const float* __restrict__ t1d,
                                               const float* __restrict__ p1w,
                                               const float* __restrict__ p1b,
                                               const float* __restrict__ c1w,
                                               const float* __restrict__ c2w,
                                               const float* __restrict__ pw,
                                               const float* __restrict__ pb) {
    __shared__ float shmem[4352];
    const int bid = blockIdx.x;
    const int tid = threadIdx.x;

    // ---- tables (block 0 only; consumed by k_pair after this kernel) ----
    if (bid == 0) {
        int l = tid;
        g_sep[l] = logf((float)l + 1.0f);
        const float c0 = -logf(10000.0f) / 32.0f;
        #pragma unroll
        for (int m = 0; m < 16; ++m) {
            float div = expf((2.0f * m) * c0);
            float a = (float)l * div;
            g_pe[l * 32 + m]      = sinf(a);
            g_pe[l * 32 + 16 + m] = cosf(a);
        }
    }

    // ---- proj1d: block = (bt, l-chunk of 16) ----
    {
        const int bt = bid >> 5;
        const int l0 = (bid & 31) * 16;
        float* st  = shmem;            // [16][46]
        float* swp = shmem + 736;      // [32][46]
        const float* tb = t1d + ((size_t)(bt * Ld + l0)) * F1Dd;
        for (int idx = tid; idx < 16 * F1Dd; idx += 512) st[idx] = tb[idx];
        for (int idx = tid; idx < Cd * F1Dd; idx += 512) swp[idx] = p1w[idx];
        __syncthreads();
        const int c = tid >> 4, ll = tid & 15;
        float acc = p1b[c];
        #pragma unroll
        for (int f = 0; f < F1Dd; ++f) acc += swp[c * F1Dd + f] * st[ll * F1Dd + f];
        g_x[(bt * Cd + c) * Ld + l0 + ll] = acc;
    }
    grid_bar(0);

    // ---- conv tower: block = (co, bt) ----
    {
        const int co = bid & 31;
        const int bt = bid >> 5;
        const int l = tid;
        float* sw = shmem;  // [32*3]
        for (int blk = 0; blk < NBLKd; ++blk) {
            // conv1 + instance_norm + elu : g_x -> g_y
            if (tid < Cd * 3) sw[tid] = c1w[((size_t)(blk * Cd + co)) * Cd * 3 + tid];
            __syncthreads();
            {
                float acc = conv_row(g_x + bt * Cd * Ld, sw, l);
                float2 s = blockReduce2(acc, acc * acc);
                float m = s.x * (1.0f / Ld);
                float var = s.y * (1.0f / Ld) - m * m;
                float v = (acc - m) * rsqrtf(var + 1e-5f);
                g_y[(bt * Cd + co) * Ld + l] = (v > 0.f) ? v : expm1f(v);
            }
            grid_bar(1 + 2 * blk);
            // conv2 + instance_norm + residual elu : g_y -> g_x
            if (tid < Cd * 3) sw[tid] = c2w[((size_t)(blk * Cd + co)) * Cd * 3 + tid];
            __syncthreads();
            {
                float acc = conv_row(g_y + bt * Cd * Ld, sw, l);
                float2 s = blockReduce2(acc, acc * acc);
                float m = s.x * (1.0f / Ld);
                float var = s.y * (1.0f / Ld) - m * m;
                float v = (acc - m) * rsqrtf(var + 1e-5f);
                int idx = (bt * Cd + co) * Ld + l;
                float xo = g_x[idx] + v;
                g_x[idx] = (xo > 0.f) ? xo : expm1f(xo);
            }
            grid_bar(2 + 2 * blk);
        }
    }

    // ---- eL/eR: 65536 threads, each handles (o, l) for 2 bt values ----
    {
        float* sWl = shmem;              // [64][33]
        float* sWr = shmem + 64 * 33;    // [64][33]
        for (int idx = tid; idx < Kd * 64; idx += 512) {
            int o = idx >> 6, c2 = idx & 63;
            float v = pw[o * PWSTRIDE + F2Dd + c2];
            if (c2 < Cd) sWl[o * 33 + c2] = v;
            else         sWr[o * 33 + (c2 - Cd)] = v;
        }
        __syncthreads();
        const int T = bid * 512 + tid;
        const int o = T & 63;
        const int lbt = T >> 6;          // 0..1023
        const int l = lbt & 511;
        const int bh = lbt >> 9;         // 0..1
        const float bias = pb[o];
        #pragma unroll
        for (int bt2 = 0; bt2 < 2; ++bt2) {
            const int bt = bh * 2 + bt2;
            float aL = bias, aR = 0.f;
            #pragma unroll
            for (int c = 0; c < Cd; ++c) {
                float e = g_x[(bt * Cd + c) * Ld + l];
                aL += sWl[o * 33 + c] * e;
                aR += sWr[o * 33 + c] * e;
            }
            g_eL[((size_t)(bt * Ld + l)) * Kd + o] = aL;
            g_eR[((size_t)(bt * Ld + l)) * Kd + o] = aR;
        }
    }
}

// ---------------------------------------------------------------------------
// pair kernel: out[row][o], row=(bt,i,j). CTA: one i, 128-j tile.
// 256 threads = 32 row-groups (4 rows) x 8 o-groups (o = og*8 + oo).
// f32x2 packed FMA in the K=44 main loop.
// ---------------------------------------------------------------------------
#define RTILE 128
#define TPAD 46

__global__ __launch_bounds__(256) void k_pair(const float* __restrict__ t2d,
                                              const float* __restrict__ pw,
                                              float* __restrict__ out) {
    __shared__ __align__(16) float sT[RTILE * TPAD];   // 23552 B
    __shared__ __align__(16) float sW[F2Dd * Kd];      // [k][o], 11264 B
    __shared__ __align__(16) float sEL[Kd];
    __shared__ __align__(16) float sWsep[Kd];
    __shared__ float sPEi[32], sSep[RTILE];

    const int tid = threadIdx.x;
    const int bidx = blockIdx.x;
    const int bt = bidx >> 11;
    const int i  = (bidx >> 2) & 511;
    const int j0 = (bidx & 3) << 7;
    const size_t rowbase = ((size_t)(bt * Ld + i)) * Ld + j0;

    // stage t2d tile: 128 rows x 44 floats = 1408 float4 (11 float4/row)
    {
        const float4* src = (const float4*)(t2d + rowbase * F2Dd);
        #pragma unroll
        for (int it = 0; it < 6; ++it) {
            int idx = tid + it * 256;
            if (it < 5 || idx < 1408) {
                float4 v = src[idx];
                int r = idx / 11, kq = idx - r * 11;
                float2* d = (float2*)(sT + r * TPAD + kq * 4);
                d[0] = make_float2(v.x, v.y);
                d[1] = make_float2(v.z, v.w);
            }
        }
    }
    // stage W2d transposed: sW[k*64 + o] = pw[o*109 + k]
    for (int idx = tid; idx < F2Dd * Kd; idx += 256) {
        int k = idx >> 6, o = idx & 63;
        sW[idx] = pw[o * PWSTRIDE + k];
    }
    if (tid < Kd) {
        sEL[tid]   = g_eL[((size_t)(bt * Ld + i)) * Kd + tid];
        sWsep[tid] = pw[tid * PWSTRIDE + (PWSTRIDE - 1)];
    }
    if (tid < 32) sPEi[tid] = g_pe[i * 32 + tid];
    if (tid < RTILE) { int j = j0 + tid; sSep[tid] = g_sep[abs(i - j)]; }
    __syncthreads();

    const int og = tid & 7;
    const int rg = tid >> 3;                  // 0..31, 4 rows each
    const float* aT = sT + rg * 4 * TPAD;
    const unsigned long long* sWq = (const unsigned long long*)sW;  // pairs (2t,2t+1)
    const int wb = og * 4;                    // o = og*8 + {0..7} -> 4 ull pairs

    unsigned long long acc[4][4];
    const unsigned long long z = pack2(0.f, 0.f);
    #pragma unroll
    for (int rr = 0; rr < 4; ++rr)
        #pragma unroll
        for (int p = 0; p < 4; ++p) acc[rr][p] = z;

    #pragma unroll 4
    for (int k = 0; k < F2Dd; ++k) {
        unsigned long long w0 = sWq[k * 32 + wb + 0];
        unsigned long long w1 = sWq[k * 32 + wb + 1];
        unsigned long long w2 = sWq[k * 32 + wb + 2];
        unsigned long long w3 = sWq[k * 32 + wb + 3];
        #pragma unroll
        for (int rr = 0; rr < 4; ++rr) {
            float a = aT[rr * TPAD + k];
            unsigned long long aa = pack2(a, a);
            acc[rr][0] = ffma2(aa, w0, acc[rr][0]);
            acc[rr][1] = ffma2(aa, w1, acc[rr][1]);
            acc[rr][2] = ffma2(aa, w2, acc[rr][2]);
            acc[rr][3] = ffma2(aa, w3, acc[rr][3]);
        }
    }

    // epilogue: o = og*8 + t, t = 0..7
    const int ob = og * 8;
    float base[8], ws[8];
    {
        float4 e0 = *(const float4*)(sEL + ob);
        float4 e1 = *(const float4*)(sEL + ob + 4);
        base[0]=e0.x; base[1]=e0.y; base[2]=e0.z; base[3]=e0.w;
        base[4]=e1.x; base[5]=e1.y; base[6]=e1.z; base[7]=e1.w;
        float4 w0 = *(const float4*)(sWsep + ob);
        float4 w1 = *(const float4*)(sWsep + ob + 4);
        ws[0]=w0.x; ws[1]=w0.y; ws[2]=w0.z; ws[3]=w0.w;
        ws[4]=w1.x; ws[5]=w1.y; ws[6]=w1.z; ws[7]=w1.w;
        if (bt == 0 && ob < 32) {
            #pragma unroll
            for (int t = 0; t < 8; ++t) base[t] += sPEi[ob + t];
        }
    }
    const bool addpeJ = (bt == 0) && (ob >= 32);
    const int jl0 = rg * 4;
    #pragma unroll
    for (int rr = 0; rr < 4; ++rr) {
        const int jl = jl0 + rr;
        const int j = j0 + jl;
        const float sep = sSep[jl];
        const float* eRp = g_eR + ((size_t)(bt * Ld + j)) * Kd + ob;
        float4 r0 = *(const float4*)(eRp);
        float4 r1 = *(const float4*)(eRp + 4);
        float v[8];
        unpack2(acc[rr][0], v[0], v[1]);
        unpack2(acc[rr][1], v[2], v[3]);
        unpack2(acc[rr][2], v[4], v[5]);
        unpack2(acc[rr][3], v[6], v[7]);
        v[0] += base[0] + r0.x + sep * ws[0];
        v[1] += base[1] + r0.y + sep * ws[1];
        v[2] += base[2] + r0.z + sep * ws[2];
        v[3] += base[3] + r0.w + sep * ws[3];
        v[4] += base[4] + r1.x + sep * ws[4];
        v[5] += base[5] + r1.y + sep * ws[5];
        v[6] += base[6] + r1.z + sep * ws[6];
        v[7] += base[7] + r1.w + sep * ws[7];
        if (addpeJ) {
            const float* pj = g_pe + j * 32 + (ob - 32);
            float4 p0 = *(const float4*)(pj);
            float4 p1 = *(const float4*)(pj + 4);
            v[0] += p0.x; v[1] += p0.y; v[2] += p0.z; v[3] += p0.w;
            v[4] += p1.x; v[5] += p1.y; v[6] += p1.z; v[7] += p1.w;
        }
        float* dst = out + (rowbase + jl) * Kd + ob;
        *(float4*)(dst)     = make_float4(v[0], v[1], v[2], v[3]);
        *(float4*)(dst + 4) = make_float4(v[4], v[5], v[6], v[7]);
    }
}

// ---------------------------------------------------------------------------
extern "C" void kernel_launch(void* const* d_in, const int* in_sizes, int n_in,
                              void* d_out, int out_size) {
    const float* t1d = (const float*)d_in[0];
    const float* t2d = (const float*)d_in[1];
    const float* p1w = (const float*)d_in[2];
    const float* p1b = (const float*)d_in[3];
    const float* c1w = (const float*)d_in[4];
    const float* c2w = (const float*)d_in[5];
    const float* pw  = (const float*)d_in[6];
    const float* pb  = (const float*)d_in[7];
    float* out = (float*)d_out;
    (void)in_sizes; (void)n_in; (void)out_size;

    k_tower<<<128, 512>>>(t1d, p1w, p1b, c1w, c2w, pw, pb);
    k_pair<<<8192, 256>>>(t2d, pw, out);
}

// round 4
// speedup vs baseline: 1.8634x; 1.8634x over previous
#include <cuda_runtime.h>
#include <math.h>

#define BTd 4
#define Ld 512
#define F1Dd 46
#define F2Dd 44
#define Cd 32
#define Kd 64
#define NBLKd 4
#define PWSTRIDE 109   // F2D + 2C + 1

// Scratch (device globals: no allocation allowed)
__device__ float g_x[BTd * Cd * Ld];
__device__ float g_y[BTd * Cd * Ld];
__device__ float g_eL[BTd * Ld * Kd];
__device__ float g_eR[BTd * Ld * Kd];
__device__ float g_pe[Ld * 32];   // pe_half: [l][0:16]=sin, [16:32]=cos
__device__ float g_sep[Ld];       // log(d+1)
__device__ unsigned g_cnt[16];    // grid-barrier slots (self-resetting)

// ---------------------------------------------------------------------------
// f32x2 packed-FMA helpers (sm_100+)
// ---------------------------------------------------------------------------
static __device__ __forceinline__ unsigned long long pack2(float x, float y) {
    unsigned long long r;
    asm("mov.b64 %0, {%1,%2};" : "=l"(r) : "f"(x), "f"(y));
    return r;
}
static __device__ __forceinline__ void unpack2(unsigned long long v, float& x, float& y) {
    asm("mov.b64 {%0,%1}, %2;" : "=f"(x), "=f"(y) : "l"(v));
}
static __device__ __forceinline__ unsigned long long ffma2(unsigned long long a,
                                                           unsigned long long b,
                                                           unsigned long long c) {
    unsigned long long d;
    asm("fma.rn.f32x2 %0, %1, %2, %3;" : "=l"(d) : "l"(a), "l"(b), "l"(c));
    return d;
}

// ---------------------------------------------------------------------------
// software grid barrier: 128 co-resident CTAs, slot b. Self-resetting.
// ---------------------------------------------------------------------------
#define NB_TOWER 128u
static __device__ __forceinline__ void grid_bar(int b) {
    __syncthreads();
    if (threadIdx.x == 0) {
        __threadfence();
        unsigned t = atomicAdd(&g_cnt[b], 1u);
        if (t < NB_TOWER - 1u) {
            while (*((volatile unsigned*)&g_cnt[b]) < NB_TOWER) {}
        }
        __threadfence();
        unsigned u = atomicAdd(&g_cnt[b], 1u);
        if (u == 2u * NB_TOWER - 1u) {
            *((volatile unsigned*)&g_cnt[b]) = 0u;
        }
    }
    __syncthreads();
}

// ---------------------------------------------------------------------------
// block reduce (512 threads): sum of (a, b) broadcast to all threads
// ---------------------------------------------------------------------------
static __device__ __forceinline__ float2 blockReduce2(float a, float b) {
    __shared__ float sa[16], sb[16], res[2];
    #pragma unroll
    for (int off = 16; off > 0; off >>= 1) {
        a += __shfl_down_sync(0xffffffffu, a, off);
        b += __shfl_down_sync(0xffffffffu, b, off);
    }
    int wid = threadIdx.x >> 5, lid = threadIdx.x & 31;
    if (lid == 0) { sa[wid] = a; sb[wid] = b; }
    __syncthreads();
    if (threadIdx.x == 0) {
        float ta = 0.f, tb = 0.f;
        #pragma unroll
        for (int i = 0; i < 16; ++i) { ta += sa[i]; tb += sb[i]; }
        res[0] = ta; res[1] = tb;
    }
    __syncthreads();
    return make_float2(res[0], res[1]);
}

static __device__ __forceinline__ float conv_row(const float* __restrict__ xb,
                                                 const float* __restrict__ sw, int l) {
    float a0 = 0.f, a1 = 0.f, a2 = 0.f, a3 = 0.f;
    #pragma unroll
    for (int ci = 0; ci < Cd; ci += 4) {
        #pragma unroll
        for (int q = 0; q < 4; ++q) {
            const float* xr = xb + (ci + q) * Ld;
            float xm = (l > 0)      ? xr[l - 1] : 0.f;
            float x0 = xr[l];
            float xp = (l < Ld - 1) ? xr[l + 1] : 0.f;
            float s = sw[(ci + q) * 3 + 0] * xm + sw[(ci + q) * 3 + 1] * x0
                    + sw[(ci + q) * 3 + 2] * xp;
            if (q == 0) a0 += s; else if (q == 1) a1 += s;
            else if (q == 2) a2 += s; else a3 += s;
        }
    }
    return (a0 + a1) + (a2 + a3);
}

// ---------------------------------------------------------------------------
// Persistent tower kernel: tables + proj1d + 4 residual blocks + eL/eR.
// grid = 128 blocks x 512 threads (single wave; software grid barriers).
// ---------------------------------------------------------------------------
__global__ __launch_bounds__(512) void k_tower(const float* __restrict__ t1d,
                                               const float* __restrict__ p1w,
                                               const float* __restrict__ p1b,
                                               const float* __restrict__ c1w,
                                               const float* __restrict__ c2w,
                                               const float* __restrict__ pw,
                                               const float* __restrict__ pb) {
    __shared__ float shmem[4352];
    const int bid = blockIdx.x;
    const int tid = threadIdx.x;

    // ---- tables (block 0 only; consumed by k_pair after this kernel) ----
    if (bid == 0) {
        int l = tid;
        g_sep[l] = logf((float)l + 1.0f);
        const float c0 = -logf(10000.0f) / 32.0f;
        #pragma unroll
        for (int m = 0; m < 16; ++m) {
            float div = expf((2.0f * m) * c0);
            float a = (float)l * div;
            g_pe[l * 32 + m]      = sinf(a);
            g_pe[l * 32 + 16 + m] = cosf(a);
        }
    }

    // ---- proj1d: block = (bt, l-chunk of 16) ----
    {
        const int bt = bid >> 5;
        const int l0 = (bid & 31) * 16;
        float* st  = shmem;            // [16][46]
        float* swp = shmem + 736;      // [32][46]
        const float* tb = t1d + ((size_t)(bt * Ld + l0)) * F1Dd;
        for (int idx = tid; idx < 16 * F1Dd; idx += 512) st[idx] = tb[idx];
        for (int idx = tid; idx < Cd * F1Dd; idx += 512) swp[idx] = p1w[idx];
        __syncthreads();
        const int c = tid >> 4, ll = tid & 15;
        float acc = p1b[c];
        #pragma unroll
        for (int f = 0; f < F1Dd; ++f) acc += swp[c * F1Dd + f] * st[ll * F1Dd + f];
        g_x[(bt * Cd + c) * Ld + l0 + ll] = acc;
    }
    grid_bar(0);

    // ---- conv tower: block = (co, bt) ----
    {
        const int co = bid & 31;
        const int bt = bid >> 5;
        const int l = tid;
        float* sw = shmem;  // [32*3]
        for (int blk = 0; blk < NBLKd; ++blk) {
            if (tid < Cd * 3) sw[tid] = c1w[((size_t)(blk * Cd + co)) * Cd * 3 + tid];
            __syncthreads();
            {
                float acc = conv_row(g_x + bt * Cd * Ld, sw, l);
                float2 s = blockReduce2(acc, acc * acc);
                float m = s.x * (1.0f / Ld);
                float var = s.y * (1.0f / Ld) - m * m;
                float v = (acc - m) * rsqrtf(var + 1e-5f);
                g_y[(bt * Cd + co) * Ld + l] = (v > 0.f) ? v : expm1f(v);
            }
            grid_bar(1 + 2 * blk);
            if (tid < Cd * 3) sw[tid] = c2w[((size_t)(blk * Cd + co)) * Cd * 3 + tid];
            __syncthreads();
            {
                float acc = conv_row(g_y + bt * Cd * Ld, sw, l);
                float2 s = blockReduce2(acc, acc * acc);
                float m = s.x * (1.0f / Ld);
                float var = s.y * (1.0f / Ld) - m * m;
                float v = (acc - m) * rsqrtf(var + 1e-5f);
                int idx = (bt * Cd + co) * Ld + l;
                float xo = g_x[idx] + v;
                g_x[idx] = (xo > 0.f) ? xo : expm1f(xo);
            }
            grid_bar(2 + 2 * blk);
        }
    }

    // ---- eL/eR ----
    {
        float* sWl = shmem;              // [64][33]
        float* sWr = shmem + 64 * 33;    // [64][33]
        for (int idx = tid; idx < Kd * 64; idx += 512) {
            int o = idx >> 6, c2 = idx & 63;
            float v = pw[o * PWSTRIDE + F2Dd + c2];
            if (c2 < Cd) sWl[o * 33 + c2] = v;
            else         sWr[o * 33 + (c2 - Cd)] = v;
        }
        __syncthreads();
        const int T = bid * 512 + tid;
        const int o = T & 63;
        const int lbt = T >> 6;
        const int l = lbt & 511;
        const int bh = lbt >> 9;
        const float bias = pb[o];
        #pragma unroll
        for (int bt2 = 0; bt2 < 2; ++bt2) {
            const int bt = bh * 2 + bt2;
            float aL = bias, aR = 0.f;
            #pragma unroll
            for (int c = 0; c < Cd; ++c) {
                float e = g_x[(bt * Cd + c) * Ld + l];
                aL += sWl[o * 33 + c] * e;
                aR += sWr[o * 33 + c] * e;
            }
            g_eL[((size_t)(bt * Ld + l)) * Kd + o] = aL;
            g_eR[((size_t)(bt * Ld + l)) * Kd + o] = aR;
        }
    }
}

// ---------------------------------------------------------------------------
// pair kernel v2: conflict-free shared layouts.
//   sA[rg][k][rr]  rg-stride 180 floats (45*4) -> 1 LDS.128 per k (banks 0/20/8/28)
//   sW [p][k][og]  -> LDS.64 lanes at og*8 B -> banks og*2, conflict-free
// 256 threads = 32 rg (4 rows) x 8 og (o = og*8 + 2p + e).
// ---------------------------------------------------------------------------
#define RTILE 128
#define RGSTRIDE 180   // 45*4 floats per rg

__global__ __launch_bounds__(256) void k_pair(const float* __restrict__ t2d,
                                              const float* __restrict__ pw,
                                              float* __restrict__ out) {
    __shared__ __align__(16) float sA[32 * RGSTRIDE];          // 23040 B
    __shared__ __align__(16) unsigned long long sWp[4 * F2Dd * 8]; // 11264 B
    __shared__ __align__(16) float sEL[Kd];
    __shared__ __align__(16) float sWsep[Kd];
    __shared__ float sPEi[32], sSep[RTILE];

    const int tid = threadIdx.x;
    const int bidx = blockIdx.x;
    const int bt = bidx >> 11;
    const int i  = (bidx >> 2) & 511;
    const int j0 = (bidx & 3) << 7;
    const size_t rowbase = ((size_t)(bt * Ld + i)) * Ld + j0;

    // stage t2d tile: 128 rows x 44 floats = 1408 float4 reads (11 per row)
    {
        const float4* src = (const float4*)(t2d + rowbase * F2Dd);
        #pragma unroll
        for (int it = 0; it < 6; ++it) {
            int idx = tid + it * 256;
            if (it < 5 || idx < 1408) {
                float4 v = src[idx];
                int r = idx / 11, kq = idx - r * 11;   // k = kq*4 .. kq*4+3
                int rg = r >> 2, rr = r & 3;
                float* d = sA + rg * RGSTRIDE + (kq * 4) * 4 + rr;
                d[0]  = v.x;
                d[4]  = v.y;
                d[8]  = v.z;
                d[12] = v.w;
            }
        }
    }
    // stage W pairs: sWp[(p*44 + k)*8 + og] = (w[o][k], w[o+1][k]), o = og*8+2p
    for (int idx = tid; idx < 4 * F2Dd * 8; idx += 256) {
        int p = idx / (F2Dd * 8);
        int rem = idx - p * (F2Dd * 8);
        int k = rem >> 3, og = rem & 7;
        int o = og * 8 + 2 * p;
        sWp[idx] = pack2(pw[o * PWSTRIDE + k], pw[(o + 1) * PWSTRIDE + k]);
    }
    if (tid < Kd) {
        sEL[tid]   = g_eL[((size_t)(bt * Ld + i)) * Kd + tid];
        sWsep[tid] = pw[tid * PWSTRIDE + (PWSTRIDE - 1)];
    }
    if (tid < 32) sPEi[tid] = g_pe[i * 32 + tid];
    if (tid < RTILE) { int j = j0 + tid; sSep[tid] = g_sep[abs(i - j)]; }
    __syncthreads();

    const int og = tid & 7;
    const int rg = tid >> 3;
    const float* aB = sA + rg * RGSTRIDE;
    const unsigned long long* w0B = sWp + og;              // p=0
    const unsigned long long* w1B = w0B + F2Dd * 8;        // p=1
    const unsigned long long* w2B = w1B + F2Dd * 8;        // p=2
    const unsigned long long* w3B = w2B + F2Dd * 8;        // p=3

    unsigned long long acc[4][4];   // [rr][p]
    const unsigned long long z = pack2(0.f, 0.f);
    #pragma unroll
    for (int rr = 0; rr < 4; ++rr)
        #pragma unroll
        for (int p = 0; p < 4; ++p) acc[rr][p] = z;

    #pragma unroll 4
    for (int k = 0; k < F2Dd; ++k) {
        float4 av = *(const float4*)(aB + k * 4);     // a for rr=0..3
        unsigned long long w0 = w0B[k * 8];
        unsigned long long w1 = w1B[k * 8];
        unsigned long long w2 = w2B[k * 8];
        unsigned long long w3 = w3B[k * 8];
        unsigned long long a0 = pack2(av.x, av.x);
        unsigned long long a1 = pack2(av.y, av.y);
        unsigned long long a2 = pack2(av.z, av.z);
        unsigned long long a3 = pack2(av.w, av.w);
        acc[0][0] = ffma2(a0, w0, acc[0][0]);
        acc[0][1] = ffma2(a0, w1, acc[0][1]);
        acc[0][2] = ffma2(a0, w2, acc[0][2]);
        acc[0][3] = ffma2(a0, w3, acc[0][3]);
        acc[1][0] = ffma2(a1, w0, acc[1][0]);
        acc[1][1] = ffma2(a1, w1, acc[1][1]);
        acc[1][2] = ffma2(a1, w2, acc[1][2]);
        acc[1][3] = ffma2(a1, w3, acc[1][3]);
        acc[2][0] = ffma2(a2, w0, acc[2][0]);
        acc[2][1] = ffma2(a2, w1, acc[2][1]);
        acc[2][2] = ffma2(a2, w2, acc[2][2]);
        acc[2][3] = ffma2(a2, w3, acc[2][3]);
        acc[3][0] = ffma2(a3, w0, acc[3][0]);
        acc[3][1] = ffma2(a3, w1, acc[3][1]);
        acc[3][2] = ffma2(a3, w2, acc[3][2]);
        acc[3][3] = ffma2(a3, w3, acc[3][3]);
    }

    // epilogue: acc[rr][p] -> v[2p], v[2p+1] with o = og*8 + 2p + e
    const int ob = og * 8;
    float base[8], ws[8];
    {
        float4 e0 = *(const float4*)(sEL + ob);
        float4 e1 = *(const float4*)(sEL + ob + 4);
        base[0]=e0.x; base[1]=e0.y; base[2]=e0.z; base[3]=e0.w;
        base[4]=e1.x; base[5]=e1.y; base[6]=e1.z; base[7]=e1.w;
        float4 w0 = *(const float4*)(sWsep + ob);
        float4 w1 = *(const float4*)(sWsep + ob + 4);
        ws[0]=w0.x; ws[1]=w0.y; ws[2]=w0.z; ws[3]=w0.w;
        ws[4]=w1.x; ws[5]=w1.y; ws[6]=w1.z; ws[7]=w1.w;
        if (bt == 0 && ob < 32) {
            #pragma unroll
            for (int t = 0; t < 8; ++t) base[t] += sPEi[ob + t];
        }
    }
    const bool addpeJ = (bt == 0) && (ob >= 32);
    const int jl0 = rg * 4;
    #pragma unroll
    for (int rr = 0; rr < 4; ++rr) {
        const int jl = jl0 + rr;
        const int j = j0 + jl;
        const float sep = sSep[jl];
        const float* eRp = g_eR + ((size_t)(bt * Ld + j)) * Kd + ob;
        float4 r0 = *(const float4*)(eRp);
        float4 r1 = *(const float4*)(eRp + 4);
        float v[8];
        unpack2(acc[rr][0], v[0], v[1]);
        unpack2(acc[rr][1], v[2], v[3]);
        unpack2(acc[rr][2], v[4], v[5]);
        unpack2(acc[rr][3], v[6], v[7]);
        v[0] += base[0] + r0.x + sep * ws[0];
        v[1] += base[1] + r0.y + sep * ws[1];
        v[2] += base[2] + r0.z + sep * ws[2];
        v[3] += base[3] + r0.w + sep * ws[3];
        v[4] += base[4] + r1.x + sep * ws[4];
        v[5] += base[5] + r1.y + sep * ws[5];
        v[6] += base[6] + r1.z + sep * ws[6];
        v[7] += base[7] + r1.w + sep * ws[7];
        if (addpeJ) {
            const float* pj = g_pe + j * 32 + (ob - 32);
            float4 p0 = *(const float4*)(pj);
            float4 p1 = *(const float4*)(pj + 4);
            v[0] += p0.x; v[1] += p0.y; v[2] += p0.z; v[3] += p0.w;
            v[4] += p1.x; v[5] += p1.y; v[6] += p1.z; v[7] += p1.w;
        }
        float* dst = out + (rowbase + jl) * Kd + ob;
        *(float4*)(dst)     = make_float4(v[0], v[1], v[2], v[3]);
        *(float4*)(dst + 4) = make_float4(v[4], v[5], v[6], v[7]);
    }
}

// ---------------------------------------------------------------------------
extern "C" void kernel_launch(void* const* d_in, const int* in_sizes, int n_in,
                              void* d_out, int out_size) {
    const float* t1d = (const float*)d_in[0];
    const float* t2d = (const float*)d_in[1];
    const float* p1w = (const float*)d_in[2];
    const float* p1b = (const float*)d_in[3];
    const float* c1w = (const float*)d_in[4];
    const float* c2w = (const float*)d_in[5];
    const float* pw  = (const float*)d_in[6];
    const float* pb  = (const float*)d_in[7];
    float* out = (float*)d_out;
    (void)in_sizes; (void)n_in; (void)out_size;

    k_tower<<<128, 512>>>(t1d, p1w, p1b, c1w, c2w, pw, pb);
    k_pair<<<8192, 256>>>(t2d, pw, out);
}

// round 5
// speedup vs baseline: 1.9684x; 1.0564x over previous
#include <cuda_runtime.h>
#include <math.h>

#define BTd 4
#define Ld 512
#define F1Dd 46
#define F2Dd 44
#define Cd 32
#define Kd 64
#define NBLKd 4
#define PWSTRIDE 109   // F2D + 2C + 1

// Scratch (device globals: no allocation allowed)
__device__ float g_x[BTd * Cd * Ld];
__device__ float g_y[BTd * Cd * Ld];
__device__ float g_eL[BTd * Ld * Kd];
__device__ float g_eR[BTd * Ld * Kd];
__device__ float g_pe[Ld * 32];   // pe_half: [l][0:16]=sin, [16:32]=cos
__device__ float g_sep[Ld];       // log(d+1)
__device__ unsigned g_cnt[16];    // grid-barrier slots (self-resetting)

// ---------------------------------------------------------------------------
// f32x2 packed-FMA helpers (sm_100+)
// ---------------------------------------------------------------------------
static __device__ __forceinline__ unsigned long long pack2(float x, float y) {
    unsigned long long r;
    asm("mov.b64 %0, {%1,%2};" : "=l"(r) : "f"(x), "f"(y));
    return r;
}
static __device__ __forceinline__ void unpack2(unsigned long long v, float& x, float& y) {
    asm("mov.b64 {%0,%1}, %2;" : "=f"(x), "=f"(y) : "l"(v));
}
static __device__ __forceinline__ unsigned long long ffma2(unsigned long long a,
                                                           unsigned long long b,
                                                           unsigned long long c) {
    unsigned long long d;
    asm("fma.rn.f32x2 %0, %1, %2, %3;" : "=l"(d) : "l"(a), "l"(b), "l"(c));
    return d;
}

// ---------------------------------------------------------------------------
// software grid barrier: 128 co-resident CTAs, slot b. Self-resetting.
// ---------------------------------------------------------------------------
#define NB_TOWER 128u
static __device__ __forceinline__ void grid_bar(int b) {
    __syncthreads();
    if (threadIdx.x == 0) {
        __threadfence();
        unsigned t = atomicAdd(&g_cnt[b], 1u);
        if (t < NB_TOWER - 1u) {
            while (*((volatile unsigned*)&g_cnt[b]) < NB_TOWER) {}
        }
        __threadfence();
        unsigned u = atomicAdd(&g_cnt[b], 1u);
        if (u == 2u * NB_TOWER - 1u) {
            *((volatile unsigned*)&g_cnt[b]) = 0u;
        }
    }
    __syncthreads();
}

// ---------------------------------------------------------------------------
// block reduce (512 threads): sum of (a, b) broadcast to all threads
// ---------------------------------------------------------------------------
static __device__ __forceinline__ float2 blockReduce2(float a, float b) {
    __shared__ float sa[16], sb[16], res[2];
    #pragma unroll
    for (int off = 16; off > 0; off >>= 1) {
        a += __shfl_down_sync(0xffffffffu, a, off);
        b += __shfl_down_sync(0xffffffffu, b, off);
    }
    int wid = threadIdx.x >> 5, lid = threadIdx.x & 31;
    if (lid == 0) { sa[wid] = a; sb[wid] = b; }
    __syncthreads();
    if (threadIdx.x == 0) {
        float ta = 0.f, tb = 0.f;
        #pragma unroll
        for (int i = 0; i < 16; ++i) { ta += sa[i]; tb += sb[i]; }
        res[0] = ta; res[1] = tb;
    }
    __syncthreads();
    return make_float2(res[0], res[1]);
}

static __device__ __forceinline__ float conv_row(const float* __restrict__ xb,
                                                 const float* __restrict__ sw, int l) {
    float a0 = 0.f, a1 = 0.f, a2 = 0.f, a3 = 0.f;
    #pragma unroll
    for (int ci = 0; ci < Cd; ci += 4) {
        #pragma unroll
        for (int q = 0; q < 4; ++q) {
            const float* xr = xb + (ci + q) * Ld;
            float xm = (l > 0)      ? xr[l - 1] : 0.f;
            float x0 = xr[l];
            float xp = (l < Ld - 1) ? xr[l + 1] : 0.f;
            float s = sw[(ci + q) * 3 + 0] * xm + sw[(ci + q) * 3 + 1] * x0
                    + sw[(ci + q) * 3 + 2] * xp;
            if (q == 0) a0 += s; else if (q == 1) a1 += s;
            else if (q == 2) a2 += s; else a3 += s;
        }
    }
    return (a0 + a1) + (a2 + a3);
}

// ---------------------------------------------------------------------------
// Persistent tower kernel: tables + proj1d + 4 residual blocks + eL/eR.
// grid = 128 blocks x 512 threads (single wave; software grid barriers).
// ---------------------------------------------------------------------------
__global__ __launch_bounds__(512) void k_tower(const float* __restrict__ t1d,
                                               const float* __restrict__ p1w,
                                               const float* __restrict__ p1b,
                                               const float* __restrict__ c1w,
                                               const float* __restrict__ c2w,
                                               const float* __restrict__ pw,
                                               const float* __restrict__ pb) {
    __shared__ float shmem[4352];
    const int bid = blockIdx.x;
    const int tid = threadIdx.x;

    // ---- tables (block 0 only; consumed by k_pair after this kernel) ----
    if (bid == 0) {
        int l = tid;
        g_sep[l] = logf((float)l + 1.0f);
        const float c0 = -logf(10000.0f) / 32.0f;
        #pragma unroll
        for (int m = 0; m < 16; ++m) {
            float div = expf((2.0f * m) * c0);
            float a = (float)l * div;
            g_pe[l * 32 + m]      = sinf(a);
            g_pe[l * 32 + 16 + m] = cosf(a);
        }
    }

    // ---- proj1d: block = (bt, l-chunk of 16) ----
    {
        const int bt = bid >> 5;
        const int l0 = (bid & 31) * 16;
        float* st  = shmem;            // [16][46]
        float* swp = shmem + 736;      // [32][46]
        const float* tb = t1d + ((size_t)(bt * Ld + l0)) * F1Dd;
        for (int idx = tid; idx < 16 * F1Dd; idx += 512) st[idx] = tb[idx];
        for (int idx = tid; idx < Cd * F1Dd; idx += 512) swp[idx] = p1w[idx];
        __syncthreads();
        const int c = tid >> 4, ll = tid & 15;
        float acc = p1b[c];
        #pragma unroll
        for (int f = 0; f < F1Dd; ++f) acc += swp[c * F1Dd + f] * st[ll * F1Dd + f];
        g_x[(bt * Cd + c) * Ld + l0 + ll] = acc;
    }
    grid_bar(0);

    // ---- conv tower: block = (co, bt) ----
    {
        const int co = bid & 31;
        const int bt = bid >> 5;
        const int l = tid;
        float* sw = shmem;  // [32*3]
        for (int blk = 0; blk < NBLKd; ++blk) {
            if (tid < Cd * 3) sw[tid] = c1w[((size_t)(blk * Cd + co)) * Cd * 3 + tid];
            __syncthreads();
            {
                float acc = conv_row(g_x + bt * Cd * Ld, sw, l);
                float2 s = blockReduce2(acc, acc * acc);
                float m = s.x * (1.0f / Ld);
                float var = s.y * (1.0f / Ld) - m * m;
                float v = (acc - m) * rsqrtf(var + 1e-5f);
                g_y[(bt * Cd + co) * Ld + l] = (v > 0.f) ? v : expm1f(v);
            }
            grid_bar(1 + 2 * blk);
            if (tid < Cd * 3) sw[tid] = c2w[((size_t)(blk * Cd + co)) * Cd * 3 + tid];
            __syncthreads();
            {
                float acc = conv_row(g_y + bt * Cd * Ld, sw, l);
                float2 s = blockReduce2(acc, acc * acc);
                float m = s.x * (1.0f / Ld);
                float var = s.y * (1.0f / Ld) - m * m;
                float v = (acc - m) * rsqrtf(var + 1e-5f);
                int idx = (bt * Cd + co) * Ld + l;
                float xo = g_x[idx] + v;
                g_x[idx] = (xo > 0.f) ? xo : expm1f(xo);
            }
            grid_bar(2 + 2 * blk);
        }
    }

    // ---- eL/eR ----
    {
        float* sWl = shmem;              // [64][33]
        float* sWr = shmem + 64 * 33;    // [64][33]
        for (int idx = tid; idx < Kd * 64; idx += 512) {
            int o = idx >> 6, c2 = idx & 63;
            float v = pw[o * PWSTRIDE + F2Dd + c2];
            if (c2 < Cd) sWl[o * 33 + c2] = v;
            else         sWr[o * 33 + (c2 - Cd)] = v;
        }
        __syncthreads();
        const int T = bid * 512 + tid;
        const int o = T & 63;
        const int lbt = T >> 6;
        const int l = lbt & 511;
        const int bh = lbt >> 9;
        const float bias = pb[o];
        #pragma unroll
        for (int bt2 = 0; bt2 < 2; ++bt2) {
            const int bt = bh * 2 + bt2;
            float aL = bias, aR = 0.f;
            #pragma unroll
            for (int c = 0; c < Cd; ++c) {
                float e = g_x[(bt * Cd + c) * Ld + l];
                aL += sWl[o * 33 + c] * e;
                aR += sWr[o * 33 + c] * e;
            }
            g_eL[((size_t)(bt * Ld + l)) * Kd + o] = aL;
            g_eR[((size_t)(bt * Ld + l)) * Kd + o] = aR;
        }
    }
}

// ---------------------------------------------------------------------------
// pair kernel v3: 3 LDS per k-step.
//   sA[rg][k][rr]   rg-stride 180 floats -> 1 LDS.128/k (banks 0/20/8/28)
//   sW4[og][89 x ulonglong2] -> 2 LDS.128/k; per-og stride 356 words
//     (356 mod 32 = 4 -> lane word-offsets og*4: conflict-free)
// 256 threads = 32 rg (4 rows) x 8 og (o = og*8 + 2p + e).
// ---------------------------------------------------------------------------
#define RTILE 128
#define RGSTRIDE 180   // 45*4 floats per rg
#define WGSTRIDE 89    // ulonglong2 per og (88 used + 1 pad)

__global__ __launch_bounds__(256) void k_pair(const float* __restrict__ t2d,
                                              const float* __restrict__ pw,
                                              float* __restrict__ out) {
    __shared__ __align__(16) float sA[32 * RGSTRIDE];        // 23040 B
    __shared__ __align__(16) ulonglong2 sW4[8 * WGSTRIDE];   // 11392 B
    __shared__ __align__(16) float sEL[Kd];
    __shared__ __align__(16) float sWsep[Kd];
    __shared__ float sPEi[32], sSep[RTILE];

    const int tid = threadIdx.x;
    const int bidx = blockIdx.x;
    const int bt = bidx >> 11;
    const int i  = (bidx >> 2) & 511;
    const int j0 = (bidx & 3) << 7;
    const size_t rowbase = ((size_t)(bt * Ld + i)) * Ld + j0;

    // stage t2d tile: 128 rows x 44 floats = 1408 float4 reads (11 per row)
    {
        const float4* src = (const float4*)(t2d + rowbase * F2Dd);
        #pragma unroll
        for (int it = 0; it < 6; ++it) {
            int idx = tid + it * 256;
            if (it < 5 || idx < 1408) {
                float4 v = src[idx];
                int r = idx / 11, kq = idx - r * 11;   // k = kq*4 .. kq*4+3
                int rg = r >> 2, rr = r & 3;
                float* d = sA + rg * RGSTRIDE + (kq * 4) * 4 + rr;
                d[0]  = v.x;
                d[4]  = v.y;
                d[8]  = v.z;
                d[12] = v.w;
            }
        }
    }
    // stage W quads: sW4[og*89 + 2k+h] = (w[o][k], w[o+1][k], w[o+2][k], w[o+3][k]),
    // o = og*8 + h*4  ->  ulonglong2 = pairs (p=2h, p=2h+1)
    for (int idx = tid; idx < 8 * WGSTRIDE; idx += 256) {
        int og = idx / WGSTRIDE, s = idx - og * WGSTRIDE;
        if (s < 88) {
            int k = s >> 1, h = s & 1;
            int o = og * 8 + h * 4;
            ((float4*)sW4)[idx] = make_float4(pw[(o + 0) * PWSTRIDE + k],
                                              pw[(o + 1) * PWSTRIDE + k],
                                              pw[(o + 2) * PWSTRIDE + k],
                                              pw[(o + 3) * PWSTRIDE + k]);
        }
    }
    if (tid < Kd) {
        sEL[tid]   = g_eL[((size_t)(bt * Ld + i)) * Kd + tid];
        sWsep[tid] = pw[tid * PWSTRIDE + (PWSTRIDE - 1)];
    }
    if (tid < 32) sPEi[tid] = g_pe[i * 32 + tid];
    if (tid < RTILE) { int j = j0 + tid; sSep[tid] = g_sep[abs(i - j)]; }
    __syncthreads();

    const int og = tid & 7;
    const int rg = tid >> 3;
    const float* aB = sA + rg * RGSTRIDE;
    const ulonglong2* wB = sW4 + og * WGSTRIDE;

    unsigned long long acc[4][4];   // [rr][p], o = og*8 + 2p + e
    const unsigned long long z = pack2(0.f, 0.f);
    #pragma unroll
    for (int rr = 0; rr < 4; ++rr)
        #pragma unroll
        for (int p = 0; p < 4; ++p) acc[rr][p] = z;

    #pragma unroll 4
    for (int k = 0; k < F2Dd; ++k) {
        float4 av = *(const float4*)(aB + k * 4);     // a for rr=0..3
        ulonglong2 q0 = wB[2 * k];        // w pairs p=0,1
        ulonglong2 q1 = wB[2 * k + 1];    // w pairs p=2,3
        unsigned long long a0 = pack2(av.x, av.x);
        unsigned long long a1 = pack2(av.y, av.y);
        unsigned long long a2 = pack2(av.z, av.z);
        unsigned long long a3 = pack2(av.w, av.w);
        acc[0][0] = ffma2(a0, q0.x, acc[0][0]);
        acc[0][1] = ffma2(a0, q0.y, acc[0][1]);
        acc[0][2] = ffma2(a0, q1.x, acc[0][2]);
        acc[0][3] = ffma2(a0, q1.y, acc[0][3]);
        acc[1][0] = ffma2(a1, q0.x, acc[1][0]);
        acc[1][1] = ffma2(a1, q0.y, acc[1][1]);
        acc[1][2] = ffma2(a1, q1.x, acc[1][2]);
        acc[1][3] = ffma2(a1, q1.y, acc[1][3]);
        acc[2][0] = ffma2(a2, q0.x, acc[2][0]);
        acc[2][1] = ffma2(a2, q0.y, acc[2][1]);
        acc[2][2] = ffma2(a2, q1.x, acc[2][2]);
        acc[2][3] = ffma2(a2, q1.y, acc[2][3]);
        acc[3][0] = ffma2(a3, q0.x, acc[3][0]);
        acc[3][1] = ffma2(a3, q0.y, acc[3][1]);
        acc[3][2] = ffma2(a3, q1.x, acc[3][2]);
        acc[3][3] = ffma2(a3, q1.y, acc[3][3]);
    }

    // epilogue: acc[rr][p] -> v[2p], v[2p+1] with o = og*8 + 2p + e
    const int ob = og * 8;
    float base[8], ws[8];
    {
        float4 e0 = *(const float4*)(sEL + ob);
        float4 e1 = *(const float4*)(sEL + ob + 4);
        base[0]=e0.x; base[1]=e0.y; base[2]=e0.z; base[3]=e0.w;
        base[4]=e1.x; base[5]=e1.y; base[6]=e1.z; base[7]=e1.w;
        float4 w0 = *(const float4*)(sWsep + ob);
        float4 w1 = *(const float4*)(sWsep + ob + 4);
        ws[0]=w0.x; ws[1]=w0.y; ws[2]=w0.z; ws[3]=w0.w;
        ws[4]=w1.x; ws[5]=w1.y; ws[6]=w1.z; ws[7]=w1.w;
        if (bt == 0 && ob < 32) {
            #pragma unroll
            for (int t = 0; t < 8; ++t) base[t] += sPEi[ob + t];
        }
    }
    const bool addpeJ = (bt == 0) && (ob >= 32);
    const int jl0 = rg * 4;
    #pragma unroll
    for (int rr = 0; rr < 4; ++rr) {
        const int jl = jl0 + rr;
        const int j = j0 + jl;
        const float sep = sSep[jl];
        const float* eRp = g_eR + ((size_t)(bt * Ld + j)) * Kd + ob;
        float4 r0 = *(const float4*)(eRp);
        float4 r1 = *(const float4*)(eRp + 4);
        float v[8];
        unpack2(acc[rr][0], v[0], v[1]);
        unpack2(acc[rr][1], v[2], v[3]);
        unpack2(acc[rr][2], v[4], v[5]);
        unpack2(acc[rr][3], v[6], v[7]);
        v[0] += base[0] + r0.x + sep * ws[0];
        v[1] += base[1] + r0.y + sep * ws[1];
        v[2] += base[2] + r0.z + sep * ws[2];
        v[3] += base[3] + r0.w + sep * ws[3];
        v[4] += base[4] + r1.x + sep * ws[4];
        v[5] += base[5] + r1.y + sep * ws[5];
        v[6] += base[6] + r1.z + sep * ws[6];
        v[7] += base[7] + r1.w + sep * ws[7];
        if (addpeJ) {
            const float* pj = g_pe + j * 32 + (ob - 32);
            float4 p0 = *(const float4*)(pj);
            float4 p1 = *(const float4*)(pj + 4);
            v[0] += p0.x; v[1] += p0.y; v[2] += p0.z; v[3] += p0.w;
            v[4] += p1.x; v[5] += p1.y; v[6] += p1.z; v[7] += p1.w;
        }
        float* dst = out + (rowbase + jl) * Kd + ob;
        *(float4*)(dst)     = make_float4(v[0], v[1], v[2], v[3]);
        *(float4*)(dst + 4) = make_float4(v[4], v[5], v[6], v[7]);
    }
}

// ---------------------------------------------------------------------------
extern "C" void kernel_launch(void* const* d_in, const int* in_sizes, int n_in,
                              void* d_out, int out_size) {
    const float* t1d = (const float*)d_in[0];
    const float* t2d = (const float*)d_in[1];
    const float* p1w = (const float*)d_in[2];
    const float* p1b = (const float*)d_in[3];
    const float* c1w = (const float*)d_in[4];
    const float* c2w = (const float*)d_in[5];
    const float* pw  = (const float*)d_in[6];
    const float* pb  = (const float*)d_in[7];
    float* out = (float*)d_out;
    (void)in_sizes; (void)n_in; (void)out_size;

    k_tower<<<128, 512>>>(t1d, p1w, p1b, c1w, c2w, pw, pb);
    k_pair<<<8192, 256>>>(t2d, pw, out);
}

// round 6
// speedup vs baseline: 1.9966x; 1.0143x over previous
#include <cuda_runtime.h>
#include <math.h>

#define BTd 4
#define Ld 512
#define F1Dd 46
#define F2Dd 44
#define Cd 32
#define Kd 64
#define NBLKd 4
#define PWSTRIDE 109   // F2D + 2C + 1

// Scratch (device globals: no allocation allowed)
__device__ float g_x[BTd * Cd * Ld];
__device__ float g_y[BTd * Cd * Ld];
__device__ float g_eL[BTd * Ld * Kd];
__device__ float g_eR[BTd * Ld * Kd];
__device__ float g_pe[Ld * 32];   // pe_half: [l][0:16]=sin, [16:32]=cos
__device__ float g_sep[Ld];       // log(d+1)
__device__ unsigned g_cnt[16];    // grid-barrier slots (self-resetting)

// ---------------------------------------------------------------------------
// f32x2 packed-FMA helpers (sm_100+)
// ---------------------------------------------------------------------------
static __device__ __forceinline__ unsigned long long pack2(float x, float y) {
    unsigned long long r;
    asm("mov.b64 %0, {%1,%2};" : "=l"(r) : "f"(x), "f"(y));
    return r;
}
static __device__ __forceinline__ void unpack2(unsigned long long v, float& x, float& y) {
    asm("mov.b64 {%0,%1}, %2;" : "=f"(x), "=f"(y) : "l"(v));
}
static __device__ __forceinline__ unsigned long long ffma2(unsigned long long a,
                                                           unsigned long long b,
                                                           unsigned long long c) {
    unsigned long long d;
    asm("fma.rn.f32x2 %0, %1, %2, %3;" : "=l"(d) : "l"(a), "l"(b), "l"(c));
    return d;
}

// ---------------------------------------------------------------------------
// software grid barrier: 128 co-resident CTAs, slot b. Self-resetting.
// ---------------------------------------------------------------------------
#define NB_TOWER 128u
static __device__ __forceinline__ void grid_bar(int b) {
    __syncthreads();
    if (threadIdx.x == 0) {
        __threadfence();
        unsigned t = atomicAdd(&g_cnt[b], 1u);
        if (t < NB_TOWER - 1u) {
            while (*((volatile unsigned*)&g_cnt[b]) < NB_TOWER) {}
        }
        __threadfence();
        unsigned u = atomicAdd(&g_cnt[b], 1u);
        if (u == 2u * NB_TOWER - 1u) {
            *((volatile unsigned*)&g_cnt[b]) = 0u;
        }
    }
    __syncthreads();
}

// ---------------------------------------------------------------------------
// block reduce (512 threads): sum of (a, b) broadcast to all threads
// ---------------------------------------------------------------------------
static __device__ __forceinline__ float2 blockReduce2(float a, float b) {
    __shared__ float sa[16], sb[16], res[2];
    #pragma unroll
    for (int off = 16; off > 0; off >>= 1) {
        a += __shfl_down_sync(0xffffffffu, a, off);
        b += __shfl_down_sync(0xffffffffu, b, off);
    }
    int wid = threadIdx.x >> 5, lid = threadIdx.x & 31;
    if (lid == 0) { sa[wid] = a; sb[wid] = b; }
    __syncthreads();
    if (threadIdx.x == 0) {
        float ta = 0.f, tb = 0.f;
        #pragma unroll
        for (int i = 0; i < 16; ++i) { ta += sa[i]; tb += sb[i]; }
        res[0] = ta; res[1] = tb;
    }
    __syncthreads();
    return make_float2(res[0], res[1]);
}

static __device__ __forceinline__ float conv_row(const float* __restrict__ xb,
                                                 const float* __restrict__ sw, int l) {
    float a0 = 0.f, a1 = 0.f, a2 = 0.f, a3 = 0.f;
    #pragma unroll
    for (int ci = 0; ci < Cd; ci += 4) {
        #pragma unroll
        for (int q = 0; q < 4; ++q) {
            const float* xr = xb + (ci + q) * Ld;
            float xm = (l > 0)      ? xr[l - 1] : 0.f;
            float x0 = xr[l];
            float xp = (l < Ld - 1) ? xr[l + 1] : 0.f;
            float s = sw[(ci + q) * 3 + 0] * xm + sw[(ci + q) * 3 + 1] * x0
                    + sw[(ci + q) * 3 + 2] * xp;
            if (q == 0) a0 += s; else if (q == 1) a1 += s;
            else if (q == 2) a2 += s; else a3 += s;
        }
    }
    return (a0 + a1) + (a2 + a3);
}

// ---------------------------------------------------------------------------
// Persistent tower kernel: tables + proj1d + 4 residual blocks + eL/eR.
// grid = 128 blocks x 512 threads (single wave; software grid barriers).
// ---------------------------------------------------------------------------
__global__ __launch_bounds__(512) void k_tower(const float* __restrict__ t1d,
                                               const float* __restrict__ p1w,
                                               const float* __restrict__ p1b,
                                               const float* __restrict__ c1w,
                                               const float* __restrict__ c2w,
                                               const float* __restrict__ pw,
                                               const float* __restrict__ pb) {
    __shared__ float shmem[4352];
    const int bid = blockIdx.x;
    const int tid = threadIdx.x;

    // ---- tables (block 0 only; consumed by k_pair after this kernel) ----
    if (bid == 0) {
        int l = tid;
        g_sep[l] = logf((float)l + 1.0f);
        const float c0 = -logf(10000.0f) / 32.0f;
        #pragma unroll
        for (int m = 0; m < 16; ++m) {
            float div = expf((2.0f * m) * c0);
            float a = (float)l * div;
            g_pe[l * 32 + m]      = sinf(a);
            g_pe[l * 32 + 16 + m] = cosf(a);
        }
    }

    // ---- proj1d: block = (bt, l-chunk of 16) ----
    {
        const int bt = bid >> 5;
        const int l0 = (bid & 31) * 16;
        float* st  = shmem;            // [16][46]
        float* swp = shmem + 736;      // [32][46]
        const float* tb = t1d + ((size_t)(bt * Ld + l0)) * F1Dd;
        for (int idx = tid; idx < 16 * F1Dd; idx += 512) st[idx] = tb[idx];
        for (int idx = tid; idx < Cd * F1Dd; idx += 512) swp[idx] = p1w[idx];
        __syncthreads();
        const int c = tid >> 4, ll = tid & 15;
        float acc = p1b[c];
        #pragma unroll
        for (int f = 0; f < F1Dd; ++f) acc += swp[c * F1Dd + f] * st[ll * F1Dd + f];
        g_x[(bt * Cd + c) * Ld + l0 + ll] = acc;
    }
    grid_bar(0);

    // ---- conv tower: block = (co, bt) ----
    {
        const int co = bid & 31;
        const int bt = bid >> 5;
        const int l = tid;
        float* sw = shmem;  // [32*3]
        for (int blk = 0; blk < NBLKd; ++blk) {
            if (tid < Cd * 3) sw[tid] = c1w[((size_t)(blk * Cd + co)) * Cd * 3 + tid];
            __syncthreads();
            {
                float acc = conv_row(g_x + bt * Cd * Ld, sw, l);
                float2 s = blockReduce2(acc, acc * acc);
                float m = s.x * (1.0f / Ld);
                float var = s.y * (1.0f / Ld) - m * m;
                float v = (acc - m) * rsqrtf(var + 1e-5f);
                g_y[(bt * Cd + co) * Ld + l] = (v > 0.f) ? v : expm1f(v);
            }
            grid_bar(1 + 2 * blk);
            if (tid < Cd * 3) sw[tid] = c2w[((size_t)(blk * Cd + co)) * Cd * 3 + tid];
            __syncthreads();
            {
                float acc = conv_row(g_y + bt * Cd * Ld, sw, l);
                float2 s = blockReduce2(acc, acc * acc);
                float m = s.x * (1.0f / Ld);
                float var = s.y * (1.0f / Ld) - m * m;
                float v = (acc - m) * rsqrtf(var + 1e-5f);
                int idx = (bt * Cd + co) * Ld + l;
                float xo = g_x[idx] + v;
                g_x[idx] = (xo > 0.f) ? xo : expm1f(xo);
            }
            grid_bar(2 + 2 * blk);
        }
    }

    // ---- eL/eR ----
    {
        float* sWl = shmem;              // [64][33]
        float* sWr = shmem + 64 * 33;    // [64][33]
        for (int idx = tid; idx < Kd * 64; idx += 512) {
            int o = idx >> 6, c2 = idx & 63;
            float v = pw[o * PWSTRIDE + F2Dd + c2];
            if (c2 < Cd) sWl[o * 33 + c2] = v;
            else         sWr[o * 33 + (c2 - Cd)] = v;
        }
        __syncthreads();
        const int T = bid * 512 + tid;
        const int o = T & 63;
        const int lbt = T >> 6;
        const int l = lbt & 511;
        const int bh = lbt >> 9;
        const float bias = pb[o];
        #pragma unroll
        for (int bt2 = 0; bt2 < 2; ++bt2) {
            const int bt = bh * 2 + bt2;
            float aL = bias, aR = 0.f;
            #pragma unroll
            for (int c = 0; c < Cd; ++c) {
                float e = g_x[(bt * Cd + c) * Ld + l];
                aL += sWl[o * 33 + c] * e;
                aR += sWr[o * 33 + c] * e;
            }
            g_eL[((size_t)(bt * Ld + l)) * Kd + o] = aL;
            g_eR[((size_t)(bt * Ld + l)) * Kd + o] = aR;
        }
    }
}

// ---------------------------------------------------------------------------
// pair kernel v4: 8 rows x 8 outputs per thread -> 4 LDS per k, 32 FFMA2.
//   128 threads = 16 rg (8 rows) x 8 og (o = og*8 + 2p + e).
//   sA[rg][k][rr8]  rg-stride 360 floats (mod 32 = 8 -> rg banks 0/8/16/24)
//   sW4[og][89 x ulonglong2] (as v3; 2 LDS.128/k, og-broadcast, conflict-free)
// ---------------------------------------------------------------------------
#define RTILE 128
#define RGS 360        // floats per rg: 44*8 + 8 pad
#define WGSTRIDE 89    // ulonglong2 per og (88 used + 1 pad)

__global__ __launch_bounds__(128, 4) void k_pair(const float* __restrict__ t2d,
                                                 const float* __restrict__ pw,
                                                 float* __restrict__ out) {
    __shared__ __align__(16) float sA[16 * RGS];             // 23040 B
    __shared__ __align__(16) ulonglong2 sW4[8 * WGSTRIDE];   // 11392 B
    __shared__ __align__(16) float sEL[Kd];
    __shared__ __align__(16) float sWsep[Kd];
    __shared__ float sPEi[32], sSep[RTILE];

    const int tid = threadIdx.x;
    const int bidx = blockIdx.x;
    const int bt = bidx >> 11;
    const int i  = (bidx >> 2) & 511;
    const int j0 = (bidx & 3) << 7;
    const size_t rowbase = ((size_t)(bt * Ld + i)) * Ld + j0;

    // stage t2d tile: 128 rows x 44 floats = 1408 float4 reads (11 per row)
    {
        const float4* src = (const float4*)(t2d + rowbase * F2Dd);
        #pragma unroll
        for (int it = 0; it < 11; ++it) {
            int idx = tid + it * 128;             // 11*128 = 1408 exactly
            float4 v = src[idx];
            int r = idx / 11, kq = idx - r * 11;  // k = kq*4 .. kq*4+3
            int rg = r >> 3, rr = r & 7;
            float* d = sA + rg * RGS + kq * 32 + rr;
            d[0]  = v.x;
            d[8]  = v.y;
            d[16] = v.z;
            d[24] = v.w;
        }
    }
    // stage W quads: sW4[og*89 + 2k+h] = w[o..o+3][k], o = og*8 + h*4
    for (int idx = tid; idx < 8 * WGSTRIDE; idx += 128) {
        int og = idx / WGSTRIDE, s = idx - og * WGSTRIDE;
        if (s < 88) {
            int k = s >> 1, h = s & 1;
            int o = og * 8 + h * 4;
            ((float4*)sW4)[idx] = make_float4(pw[(o + 0) * PWSTRIDE + k],
                                              pw[(o + 1) * PWSTRIDE + k],
                                              pw[(o + 2) * PWSTRIDE + k],
                                              pw[(o + 3) * PWSTRIDE + k]);
        }
    }
    if (tid < Kd) {
        sEL[tid]   = g_eL[((size_t)(bt * Ld + i)) * Kd + tid];
        sWsep[tid] = pw[tid * PWSTRIDE + (PWSTRIDE - 1)];
    }
    if (tid < 32) sPEi[tid] = g_pe[i * 32 + tid];
    { int j = j0 + tid; sSep[tid] = g_sep[abs(i - j)]; }   // 128 threads = 128 j
    __syncthreads();

    const int og = tid & 7;
    const int rg = tid >> 3;             // 0..15, 8 rows each
    const float* aB = sA + rg * RGS;
    const ulonglong2* wB = sW4 + og * WGSTRIDE;

    unsigned long long acc[8][4];        // [rr][p], o = og*8 + 2p + e
    const unsigned long long z = pack2(0.f, 0.f);
    #pragma unroll
    for (int rr = 0; rr < 8; ++rr)
        #pragma unroll
        for (int p = 0; p < 4; ++p) acc[rr][p] = z;

    #pragma unroll 2
    for (int k = 0; k < F2Dd; ++k) {
        float4 av0 = *(const float4*)(aB + k * 8);       // rows 0..3
        float4 av1 = *(const float4*)(aB + k * 8 + 4);   // rows 4..7
        ulonglong2 q0 = wB[2 * k];        // w pairs p=0,1
        ulonglong2 q1 = wB[2 * k + 1];    // w pairs p=2,3
        unsigned long long a;
        a = pack2(av0.x, av0.x);
        acc[0][0] = ffma2(a, q0.x, acc[0][0]);
        acc[0][1] = ffma2(a, q0.y, acc[0][1]);
        acc[0][2] = ffma2(a, q1.x, acc[0][2]);
        acc[0][3] = ffma2(a, q1.y, acc[0][3]);
        a = pack2(av0.y, av0.y);
        acc[1][0] = ffma2(a, q0.x, acc[1][0]);
        acc[1][1] = ffma2(a, q0.y, acc[1][1]);
        acc[1][2] = ffma2(a, q1.x, acc[1][2]);
        acc[1][3] = ffma2(a, q1.y, acc[1][3]);
        a = pack2(av0.z, av0.z);
        acc[2][0] = ffma2(a, q0.x, acc[2][0]);
        acc[2][1] = ffma2(a, q0.y, acc[2][1]);
        acc[2][2] = ffma2(a, q1.x, acc[2][2]);
        acc[2][3] = ffma2(a, q1.y, acc[2][3]);
        a = pack2(av0.w, av0.w);
        acc[3][0] = ffma2(a, q0.x, acc[3][0]);
        acc[3][1] = ffma2(a, q0.y, acc[3][1]);
        acc[3][2] = ffma2(a, q1.x, acc[3][2]);
        acc[3][3] = ffma2(a, q1.y, acc[3][3]);
        a = pack2(av1.x, av1.x);
        acc[4][0] = ffma2(a, q0.x, acc[4][0]);
        acc[4][1] = ffma2(a, q0.y, acc[4][1]);
        acc[4][2] = ffma2(a, q1.x, acc[4][2]);
        acc[4][3] = ffma2(a, q1.y, acc[4][3]);
        a = pack2(av1.y, av1.y);
        acc[5][0] = ffma2(a, q0.x, acc[5][0]);
        acc[5][1] = ffma2(a, q0.y, acc[5][1]);
        acc[5][2] = ffma2(a, q1.x, acc[5][2]);
        acc[5][3] = ffma2(a, q1.y, acc[5][3]);
        a = pack2(av1.z, av1.z);
        acc[6][0] = ffma2(a, q0.x, acc[6][0]);
        acc[6][1] = ffma2(a, q0.y, acc[6][1]);
        acc[6][2] = ffma2(a, q1.x, acc[6][2]);
        acc[6][3] = ffma2(a, q1.y, acc[6][3]);
        a = pack2(av1.w, av1.w);
        acc[7][0] = ffma2(a, q0.x, acc[7][0]);
        acc[7][1] = ffma2(a, q0.y, acc[7][1]);
        acc[7][2] = ffma2(a, q1.x, acc[7][2]);
        acc[7][3] = ffma2(a, q1.y, acc[7][3]);
    }

    // epilogue: acc[rr][p] -> v[2p], v[2p+1] with o = og*8 + 2p + e
    const int ob = og * 8;
    float base[8], ws[8];
    {
        float4 e0 = *(const float4*)(sEL + ob);
        float4 e1 = *(const float4*)(sEL + ob + 4);
        base[0]=e0.x; base[1]=e0.y; base[2]=e0.z; base[3]=e0.w;
        base[4]=e1.x; base[5]=e1.y; base[6]=e1.z; base[7]=e1.w;
        float4 w0 = *(const float4*)(sWsep + ob);
        float4 w1 = *(const float4*)(sWsep + ob + 4);
        ws[0]=w0.x; ws[1]=w0.y; ws[2]=w0.z; ws[3]=w0.w;
        ws[4]=w1.x; ws[5]=w1.y; ws[6]=w1.z; ws[7]=w1.w;
        if (bt == 0 && ob < 32) {
            #pragma unroll
            for (int t = 0; t < 8; ++t) base[t] += sPEi[ob + t];
        }
    }
    const bool addpeJ = (bt == 0) && (ob >= 32);
    const int jl0 = rg * 8;
    #pragma unroll
    for (int rr = 0; rr < 8; ++rr) {
        const int jl = jl0 + rr;
        const int j = j0 + jl;
        const float sep = sSep[jl];
        const float* eRp = g_eR + ((size_t)(bt * Ld + j)) * Kd + ob;
        float4 r0 = *(const float4*)(eRp);
        float4 r1 = *(const float4*)(eRp + 4);
        float v[8];
        unpack2(acc[rr][0], v[0], v[1]);
        unpack2(acc[rr][1], v[2], v[3]);
        unpack2(acc[rr][2], v[4], v[5]);
        unpack2(acc[rr][3], v[6], v[7]);
        v[0] += base[0] + r0.x + sep * ws[0];
        v[1] += base[1] + r0.y + sep * ws[1];
        v[2] += base[2] + r0.z + sep * ws[2];
        v[3] += base[3] + r0.w + sep * ws[3];
        v[4] += base[4] + r1.x + sep * ws[4];
        v[5] += base[5] + r1.y + sep * ws[5];
        v[6] += base[6] + r1.z + sep * ws[6];
        v[7] += base[7] + r1.w + sep * ws[7];
        if (addpeJ) {
            const float* pj = g_pe + j * 32 + (ob - 32);
            float4 p0 = *(const float4*)(pj);
            float4 p1 = *(const float4*)(pj + 4);
            v[0] += p0.x; v[1] += p0.y; v[2] += p0.z; v[3] += p0.w;
            v[4] += p1.x; v[5] += p1.y; v[6] += p1.z; v[7] += p1.w;
        }
        float* dst = out + (rowbase + jl) * Kd + ob;
        *(float4*)(dst)     = make_float4(v[0], v[1], v[2], v[3]);
        *(float4*)(dst + 4) = make_float4(v[4], v[5], v[6], v[7]);
    }
}

// ---------------------------------------------------------------------------
extern "C" void kernel_launch(void* const* d_in, const int* in_sizes, int n_in,
                              void* d_out, int out_size) {
    const float* t1d = (const float*)d_in[0];
    const float* t2d = (const float*)d_in[1];
    const float* p1w = (const float*)d_in[2];
    const float* p1b = (const float*)d_in[3];
    const float* c1w = (const float*)d_in[4];
    const float* c2w = (const float*)d_in[5];
    const float* pw  = (const float*)d_in[6];
    const float* pb  = (const float*)d_in[7];
    float* out = (float*)d_out;
    (void)in_sizes; (void)n_in; (void)out_size;

    k_tower<<<128, 512>>>(t1d, p1w, p1b, c1w, c2w, pw, pb);
    k_pair<<<8192, 128>>>(t2d, pw, out);
}